// round 2
// baseline (speedup 1.0000x reference)
#include <cuda_runtime.h>
#include <math.h>

// Problem constants (fixed by setup_inputs)
#define BSZ    2
#define LSEQ   4096
#define NH     16
#define HD     128
#define NSTATE 256
#define CHUNK_ 256
#define NCH    16      // LSEQ / CHUNK_
#define NBB    4       // 2*BSZ virtual batch-directions
#define DIN    2048    // NH*HD

// -------- static device scratch (no allocations allowed) --------
__device__ float g_Bt [(size_t)NBB*NCH*NSTATE*CHUNK_];   // [z][n][k]  B transposed
__device__ float g_Ct [(size_t)NBB*NCH*NSTATE*CHUNK_];   // [z][n][i]  C transposed
__device__ float g_CBT[(size_t)NBB*NCH*CHUNK_*CHUNK_];   // [z][k][i]  CB transposed
__device__ float g_states[(size_t)NBB*NCH*NH*NSTATE*HD]; // [z][h][n][p] -> prev after scan
__device__ float g_ybuf[(size_t)NBB*LSEQ*DIN];
__device__ float g_E   [(size_t)NBB*NH*LSEQ];            // exp(cs)
__device__ float g_Binv[(size_t)NBB*NH*LSEQ];            // dt * exp(-cs)
__device__ float g_Wst [(size_t)NBB*NH*LSEQ];            // dt * exp(cs_last - cs)
__device__ float g_cd  [NBB*NCH*NH];                     // exp(cs_last)

__device__ __forceinline__ size_t src_row(int bb, int t) {
    return (size_t)(bb & 1) * LSEQ + (size_t)(bb < 2 ? t : (LSEQ - 1 - t));
}

// ---------------- K1: softplus, per-chunk cumsum, exp factors ----------------
__global__ void k_pre(const float* __restrict__ dt, const float* __restrict__ A_log) {
    int c = blockIdx.x, h = blockIdx.y, bb = blockIdx.z;
    int i = threadIdx.x;
    int t = c * CHUNK_ + i;
    int trow = (bb < 2) ? t : (LSEQ - 1 - t);
    int ch   = (bb < 2) ? h : (h + NH);
    float dtv = dt[((size_t)(bb & 1) * LSEQ + trow) * (2 * NH) + ch];
    float ds  = (dtv > 20.f) ? dtv : log1pf(expf(dtv));
    float A   = -expf(A_log[h]);
    float dA  = ds * A;

    __shared__ float s[CHUNK_];
    s[i] = dA;
    __syncthreads();
    for (int off = 1; off < CHUNK_; off <<= 1) {
        float tv = (i >= off) ? s[i - off] : 0.f;
        __syncthreads();
        s[i] += tv;
        __syncthreads();
    }
    float cs = s[i];
    float cl = s[CHUNK_ - 1];
    size_t base = ((size_t)bb * NH + h) * LSEQ + t;
    g_E[base]    = expf(cs);
    g_Binv[base] = ds * expf(-cs);
    g_Wst[base]  = ds * expf(cl - cs);
    if (i == 0) g_cd[(bb * NCH + c) * NH + h] = expf(cl);
}

// ---------------- K0: transpose B and C per (dir,chunk) ----------------
__global__ void k_transpose(const float* __restrict__ BC) {
    int z = blockIdx.z;
    int c = z % NCH;
    int bb = z / NCH;
    int tBase = blockIdx.x * 32, chBase = blockIdx.y * 32;
    __shared__ float s[32][33];
    int lr = threadIdx.x >> 5;   // 0..7
    int lc = threadIdx.x & 31;
#pragma unroll
    for (int j = 0; j < 4; j++) {
        int r = lr + j * 8;
        int t = c * CHUNK_ + tBase + r;
        s[r][lc] = BC[src_row(bb, t) * (2 * NSTATE) + chBase + lc];
    }
    __syncthreads();
    float* outp = (chBase < NSTATE) ? g_Bt : g_Ct;
    int nOff = (chBase < NSTATE) ? chBase : (chBase - NSTATE);
#pragma unroll
    for (int j = 0; j < 4; j++) {
        int nl = lr + j * 8;
        outp[((size_t)z * NSTATE + nOff + nl) * CHUNK_ + tBase + lc] = s[lc][nl];
    }
}

// ---------------- K2: CBT[k][i] = sum_n B[k,n] C[i,n] ----------------
__global__ void k_cb() {
    int z = blockIdx.z;
    const float* Aop = g_Bt + (size_t)z * NSTATE * CHUNK_;  // [n][k]
    const float* Bop = g_Ct + (size_t)z * NSTATE * CHUNK_;  // [n][i]
    float* outp = g_CBT + (size_t)z * CHUNK_ * CHUNK_;
    int rowBase = blockIdx.x * 128;   // k
    int colBase = blockIdx.y * 128;   // i

    __shared__ __align__(16) float As[16][136];
    __shared__ __align__(16) float Bs[16][136];
    float acc[8][8] = {};
    int tx = threadIdx.x % 16, ty = threadIdx.x / 16;
    int lkk = threadIdx.x / 16, lcol = (threadIdx.x % 16) * 8;

    for (int n0 = 0; n0 < NSTATE; n0 += 16) {
        const float* pa = Aop + (size_t)(n0 + lkk) * CHUNK_ + rowBase + lcol;
        const float* pb = Bop + (size_t)(n0 + lkk) * CHUNK_ + colBase + lcol;
        *(float4*)&As[lkk][lcol]     = *(const float4*)pa;
        *(float4*)&As[lkk][lcol + 4] = *(const float4*)(pa + 4);
        *(float4*)&Bs[lkk][lcol]     = *(const float4*)pb;
        *(float4*)&Bs[lkk][lcol + 4] = *(const float4*)(pb + 4);
        __syncthreads();
#pragma unroll
        for (int kk = 0; kk < 16; kk++) {
            float a[8], b[8];
            *(float4*)&a[0] = *(const float4*)&As[kk][ty * 8];
            *(float4*)&a[4] = *(const float4*)&As[kk][ty * 8 + 4];
            *(float4*)&b[0] = *(const float4*)&Bs[kk][tx * 8];
            *(float4*)&b[4] = *(const float4*)&Bs[kk][tx * 8 + 4];
#pragma unroll
            for (int u = 0; u < 8; u++)
#pragma unroll
                for (int v = 0; v < 8; v++) acc[u][v] += a[u] * b[v];
        }
        __syncthreads();
    }
#pragma unroll
    for (int u = 0; u < 8; u++) {
        float* orow = outp + (size_t)(rowBase + ty * 8 + u) * CHUNK_ + colBase + tx * 8;
        *(float4*)orow       = make_float4(acc[u][0], acc[u][1], acc[u][2], acc[u][3]);
        *(float4*)(orow + 4) = make_float4(acc[u][4], acc[u][5], acc[u][6], acc[u][7]);
    }
}

// ---------------- K3: states[n][p] = sum_k (w_k B[k,n]) x[k,h,p] ----------------
__global__ void k_states(const float* __restrict__ x, const float* __restrict__ BC) {
    int z = blockIdx.z;
    int c = z % NCH;
    int bb = z / NCH;
    int h = blockIdx.y;
    int nBase = blockIdx.x * 128;

    __shared__ __align__(16) float As[16][136];
    __shared__ __align__(16) float Bs[16][136];
    float acc[8][8] = {};
    int tx = threadIdx.x % 16, ty = threadIdx.x / 16;
    int lkk = threadIdx.x / 16, lcol = (threadIdx.x % 16) * 8;

    for (int k0 = 0; k0 < CHUNK_; k0 += 16) {
        int t = c * CHUNK_ + k0 + lkk;
        size_t r = src_row(bb, t);
        float w = g_Wst[((size_t)bb * NH + h) * LSEQ + t];
        const float* brow = BC + r * (2 * NSTATE) + nBase + lcol;
        float4 a0 = *(const float4*)brow;
        float4 a1 = *(const float4*)(brow + 4);
        a0.x *= w; a0.y *= w; a0.z *= w; a0.w *= w;
        a1.x *= w; a1.y *= w; a1.z *= w; a1.w *= w;
        *(float4*)&As[lkk][lcol]     = a0;
        *(float4*)&As[lkk][lcol + 4] = a1;
        const float* xrow = x + r * DIN + h * HD + lcol;
        *(float4*)&Bs[lkk][lcol]     = *(const float4*)xrow;
        *(float4*)&Bs[lkk][lcol + 4] = *(const float4*)(xrow + 4);
        __syncthreads();
#pragma unroll
        for (int kk = 0; kk < 16; kk++) {
            float a[8], b[8];
            *(float4*)&a[0] = *(const float4*)&As[kk][ty * 8];
            *(float4*)&a[4] = *(const float4*)&As[kk][ty * 8 + 4];
            *(float4*)&b[0] = *(const float4*)&Bs[kk][tx * 8];
            *(float4*)&b[4] = *(const float4*)&Bs[kk][tx * 8 + 4];
#pragma unroll
            for (int u = 0; u < 8; u++)
#pragma unroll
                for (int v = 0; v < 8; v++) acc[u][v] += a[u] * b[v];
        }
        __syncthreads();
    }
    size_t sb = ((size_t)z * NH + h) * NSTATE * HD;
#pragma unroll
    for (int u = 0; u < 8; u++) {
        float* orow = g_states + sb + (size_t)(nBase + ty * 8 + u) * HD + tx * 8;
        *(float4*)orow       = make_float4(acc[u][0], acc[u][1], acc[u][2], acc[u][3]);
        *(float4*)(orow + 4) = make_float4(acc[u][4], acc[u][5], acc[u][6], acc[u][7]);
    }
}

// ---------------- K4: inter-chunk scan (in place: states -> prev) ----------------
__global__ void k_scan() {
    int idx = blockIdx.x * blockDim.x + threadIdx.x;
    int p = idx & (HD - 1);
    int n = (idx / HD) & (NSTATE - 1);
    int h = (idx / (HD * NSTATE)) & (NH - 1);
    int bb = idx / (HD * NSTATE * NH);
    size_t rest = ((size_t)h * NSTATE + n) * HD + p;
    size_t stride = (size_t)NH * NSTATE * HD;
    float carry = 0.f;
    for (int c = 0; c < NCH; c++) {
        size_t off = (size_t)(bb * NCH + c) * stride + rest;
        float sv = g_states[off];
        g_states[off] = carry;
        carry = carry * g_cd[(bb * NCH + c) * NH + h] + sv;
    }
}

// ---------------- K5: y = e_i * ( (CBT*binv*mask) @ X + C @ prev ) ----------------
__global__ void k_y(const float* __restrict__ x) {
    int z = blockIdx.z;
    int c = z % NCH;
    int bb = z / NCH;
    int h = blockIdx.y;
    int iBase = blockIdx.x * 128;

    __shared__ __align__(16) float As[16][136];
    __shared__ __align__(16) float Bs[16][136];
    float acc[8][8] = {};
    int tx = threadIdx.x % 16, ty = threadIdx.x / 16;
    int lkk = threadIdx.x / 16, lcol = (threadIdx.x % 16) * 8;

    // phase 1: intra-chunk, reduce over k
    const float* CBT = g_CBT + (size_t)z * CHUNK_ * CHUNK_;
    for (int k0 = 0; k0 < CHUNK_; k0 += 16) {
        int kg = k0 + lkk;
        int t = c * CHUNK_ + kg;
        float binv = g_Binv[((size_t)bb * NH + h) * LSEQ + t];
        const float* crow = CBT + (size_t)kg * CHUNK_ + iBase + lcol;
        float4 a0 = *(const float4*)crow;
        float4 a1 = *(const float4*)(crow + 4);
        int ig = iBase + lcol;
        a0.x = (kg <= ig + 0) ? a0.x * binv : 0.f;
        a0.y = (kg <= ig + 1) ? a0.y * binv : 0.f;
        a0.z = (kg <= ig + 2) ? a0.z * binv : 0.f;
        a0.w = (kg <= ig + 3) ? a0.w * binv : 0.f;
        a1.x = (kg <= ig + 4) ? a1.x * binv : 0.f;
        a1.y = (kg <= ig + 5) ? a1.y * binv : 0.f;
        a1.z = (kg <= ig + 6) ? a1.z * binv : 0.f;
        a1.w = (kg <= ig + 7) ? a1.w * binv : 0.f;
        *(float4*)&As[lkk][lcol]     = a0;
        *(float4*)&As[lkk][lcol + 4] = a1;
        size_t r = src_row(bb, t);
        const float* xrow = x + r * DIN + h * HD + lcol;
        *(float4*)&Bs[lkk][lcol]     = *(const float4*)xrow;
        *(float4*)&Bs[lkk][lcol + 4] = *(const float4*)(xrow + 4);
        __syncthreads();
#pragma unroll
        for (int kk = 0; kk < 16; kk++) {
            float a[8], b[8];
            *(float4*)&a[0] = *(const float4*)&As[kk][ty * 8];
            *(float4*)&a[4] = *(const float4*)&As[kk][ty * 8 + 4];
            *(float4*)&b[0] = *(const float4*)&Bs[kk][tx * 8];
            *(float4*)&b[4] = *(const float4*)&Bs[kk][tx * 8 + 4];
#pragma unroll
            for (int u = 0; u < 8; u++)
#pragma unroll
                for (int v = 0; v < 8; v++) acc[u][v] += a[u] * b[v];
        }
        __syncthreads();
    }

    // phase 2: inter-chunk, reduce over n
    const float* Ct = g_Ct + (size_t)z * NSTATE * CHUNK_;
    const float* prev = g_states + ((size_t)z * NH + h) * NSTATE * HD;
    for (int n0 = 0; n0 < NSTATE; n0 += 16) {
        const float* crow = Ct + (size_t)(n0 + lkk) * CHUNK_ + iBase + lcol;
        *(float4*)&As[lkk][lcol]     = *(const float4*)crow;
        *(float4*)&As[lkk][lcol + 4] = *(const float4*)(crow + 4);
        const float* prow = prev + (size_t)(n0 + lkk) * HD + lcol;
        *(float4*)&Bs[lkk][lcol]     = *(const float4*)prow;
        *(float4*)&Bs[lkk][lcol + 4] = *(const float4*)(prow + 4);
        __syncthreads();
#pragma unroll
        for (int kk = 0; kk < 16; kk++) {
            float a[8], b[8];
            *(float4*)&a[0] = *(const float4*)&As[kk][ty * 8];
            *(float4*)&a[4] = *(const float4*)&As[kk][ty * 8 + 4];
            *(float4*)&b[0] = *(const float4*)&Bs[kk][tx * 8];
            *(float4*)&b[4] = *(const float4*)&Bs[kk][tx * 8 + 4];
#pragma unroll
            for (int u = 0; u < 8; u++)
#pragma unroll
                for (int v = 0; v < 8; v++) acc[u][v] += a[u] * b[v];
        }
        __syncthreads();
    }

    // epilogue: scale rows by exp(cs_i), write y
#pragma unroll
    for (int u = 0; u < 8; u++) {
        int ig = iBase + ty * 8 + u;
        int t = c * CHUNK_ + ig;
        float e = g_E[((size_t)bb * NH + h) * LSEQ + t];
        float* yr = g_ybuf + ((size_t)bb * LSEQ + t) * DIN + h * HD + tx * 8;
        *(float4*)yr       = make_float4(acc[u][0] * e, acc[u][1] * e, acc[u][2] * e, acc[u][3] * e);
        *(float4*)(yr + 4) = make_float4(acc[u][4] * e, acc[u][5] * e, acc[u][6] * e, acc[u][7] * e);
    }
}

// ---------------- K6: gate GEMV + roll/flip combine ----------------
__global__ void k_final(const float* __restrict__ x, const float* __restrict__ W,
                        const float* __restrict__ Dp, float* __restrict__ out) {
    int t = blockIdx.x;
    int b = blockIdx.y;
    __shared__ float xs[DIN];
    __shared__ float gate[NH];
    const float* xrow = x + ((size_t)b * LSEQ + t) * DIN;
    for (int d = threadIdx.x; d < DIN; d += 256) xs[d] = xrow[d];
    __syncthreads();
    int warp = threadIdx.x / 32, lane = threadIdx.x % 32;
#pragma unroll
    for (int hh = 0; hh < 2; hh++) {
        int h = warp * 2 + hh;
        const float* wrow = W + (size_t)h * DIN;
        float acc = 0.f;
        for (int d = lane; d < DIN; d += 32) acc += xs[d] * wrow[d];
#pragma unroll
        for (int o = 16; o; o >>= 1) acc += __shfl_down_sync(0xFFFFFFFFu, acc, o);
        if (lane == 0) gate[h] = acc + Dp[h];
    }
    __syncthreads();
    const float* yf = (t == 0) ? nullptr : (g_ybuf + ((size_t)b * LSEQ + (t - 1)) * DIN);
    int tb = LSEQ - 1 - t;
    const float* yb = (tb == 0) ? nullptr : (g_ybuf + ((size_t)(b + 2) * LSEQ + (tb - 1)) * DIN);
    float* orow = out + ((size_t)b * LSEQ + t) * DIN;
    for (int d = threadIdx.x; d < DIN; d += 256) {
        float v = xs[d] * gate[d >> 7];
        if (yf) v += yf[d];
        if (yb) v += yb[d];
        orow[d] = v;
    }
}

// ---------------- launch ----------------
extern "C" void kernel_launch(void* const* d_in, const int* in_sizes, int n_in,
                              void* d_out, int out_size) {
    const float* x     = (const float*)d_in[0];
    const float* BC    = (const float*)d_in[1];
    const float* dt    = (const float*)d_in[2];
    const float* A_log = (const float*)d_in[3];
    const float* Dv    = (const float*)d_in[4];
    const float* W     = (const float*)d_in[5];
    float* out = (float*)d_out;

    k_pre      <<<dim3(NCH, NH, NBB), 256>>>(dt, A_log);
    k_transpose<<<dim3(8, 16, NBB * NCH), 256>>>(BC);
    k_cb       <<<dim3(2, 2, NBB * NCH), 256>>>();
    k_states   <<<dim3(2, NH, NBB * NCH), 256>>>(x, BC);
    k_scan     <<<(NBB * NH * NSTATE * HD) / 256, 256>>>();
    k_y        <<<dim3(2, NH, NBB * NCH), 256>>>(x);
    k_final    <<<dim3(LSEQ, BSZ), 256>>>(x, W, Dv, out);
}

// round 4
// speedup vs baseline: 1.0919x; 1.0919x over previous
#include <cuda_runtime.h>
#include <cuda_bf16.h>
#include <mma.h>
#include <math.h>
#include <stdint.h>

using namespace nvcuda;

#define BSZ    2
#define LSEQ   4096
#define NH     16
#define HD     128
#define NSTATE 256
#define CHUNK_ 256
#define NCH    16
#define NBB    4
#define DIN    2048
#define ZTOT   64

// ---------------- static device scratch ----------------
__device__ float g_E   [(size_t)NBB*NH*LSEQ];
__device__ float g_Binv[(size_t)NBB*NH*LSEQ];
__device__ float g_Wst [(size_t)NBB*NH*LSEQ];
__device__ float g_cd  [ZTOT*NH];
__device__ float g_Xt  [(size_t)NBB*DIN*LSEQ];          // [bb][h*128+p][t]
__device__ float g_Bt  [(size_t)ZTOT*NSTATE*CHUNK_];    // [z][n][k]
__device__ float g_CB  [(size_t)ZTOT*CHUNK_*CHUNK_];    // [z][i][k] (unmasked; mask at use)
__device__ float g_S   [(size_t)ZTOT*NH*HD*NSTATE];     // [z][h][p][n]
__device__ float g_ybuf[(size_t)NBB*NH*LSEQ*HD];        // [bb][h][t][p]  (raw, no e scale)

__device__ __forceinline__ size_t src_row(int bb, int t) {
    return (size_t)(bb & 1) * LSEQ + (size_t)(bb < 2 ? t : (LSEQ - 1 - t));
}

// ---------------- generic 128x128 WMMA tile driver, hi/lo split ----------------
// loadA/loadB(row 0..127, colBase (mult of 16), v[16]) fill fp32 source values.
template <typename LA, typename LB>
__device__ __forceinline__ void gemm128(int nkb, LA loadA, LB loadB, float* out, int ldOut) {
    __shared__ __align__(32) __nv_bfloat16 Ah[128][40];
    __shared__ __align__(32) __nv_bfloat16 Al[128][40];
    __shared__ __align__(32) __nv_bfloat16 Bh[128][40];
    __shared__ __align__(32) __nv_bfloat16 Bl[128][40];

    wmma::fragment<wmma::accumulator, 16, 16, 16, float> acc[2][4];
#pragma unroll
    for (int i = 0; i < 2; i++)
#pragma unroll
        for (int j = 0; j < 4; j++) wmma::fill_fragment(acc[i][j], 0.0f);

    const int tid = threadIdx.x;
    const int warp = tid >> 5;
    const int wr = warp >> 1;          // 0..3  (32-row band)
    const int wc = warp & 1;           // 0..1  (64-col band)
    const int srow = tid >> 1;
    const int sh = (tid & 1) * 16;

    for (int kb = 0; kb < nkb; kb++) {
        float va[16], vb[16];
        loadA(srow, kb * 32 + sh, va);
        loadB(srow, kb * 32 + sh, vb);
#pragma unroll
        for (int j = 0; j < 16; j++) {
            float v = va[j];
            __nv_bfloat16 hh = __float2bfloat16(v);
            Ah[srow][sh + j] = hh;
            Al[srow][sh + j] = __float2bfloat16(v - __bfloat162float(hh));
            v = vb[j];
            hh = __float2bfloat16(v);
            Bh[srow][sh + j] = hh;
            Bl[srow][sh + j] = __float2bfloat16(v - __bfloat162float(hh));
        }
        __syncthreads();
#pragma unroll
        for (int ks = 0; ks < 32; ks += 16) {
#pragma unroll
            for (int pass = 0; pass < 3; pass++) {
                const __nv_bfloat16 (*SA)[40] = (pass == 2) ? Al : Ah;
                const __nv_bfloat16 (*SB)[40] = (pass == 1) ? Bl : Bh;
                wmma::fragment<wmma::matrix_a, 16, 16, 16, __nv_bfloat16, wmma::row_major> af[2];
                wmma::load_matrix_sync(af[0], &SA[wr * 32][ks], 40);
                wmma::load_matrix_sync(af[1], &SA[wr * 32 + 16][ks], 40);
                wmma::fragment<wmma::matrix_b, 16, 16, 16, __nv_bfloat16, wmma::col_major> bf[4];
#pragma unroll
                for (int j = 0; j < 4; j++)
                    wmma::load_matrix_sync(bf[j], &SB[wc * 64 + j * 16][ks], 40);
#pragma unroll
                for (int i = 0; i < 2; i++)
#pragma unroll
                    for (int j = 0; j < 4; j++)
                        wmma::mma_sync(acc[i][j], af[i], bf[j], acc[i][j]);
            }
        }
        __syncthreads();
    }
#pragma unroll
    for (int i = 0; i < 2; i++)
#pragma unroll
        for (int j = 0; j < 4; j++)
            wmma::store_matrix_sync(out + (size_t)(wr * 32 + i * 16) * ldOut + wc * 64 + j * 16,
                                    acc[i][j], ldOut, wmma::mem_row_major);
}

// ---------------- K1: softplus, cumsum, exp factors ----------------
__global__ void k_pre(const float* __restrict__ dt, const float* __restrict__ A_log) {
    int c = blockIdx.x, h = blockIdx.y, bb = blockIdx.z;
    int i = threadIdx.x;
    int t = c * CHUNK_ + i;
    int trow = (bb < 2) ? t : (LSEQ - 1 - t);
    int ch   = (bb < 2) ? h : (h + NH);
    float dtv = dt[((size_t)(bb & 1) * LSEQ + trow) * (2 * NH) + ch];
    float ds  = (dtv > 20.f) ? dtv : log1pf(expf(dtv));
    float dA  = ds * (-expf(A_log[h]));
    __shared__ float s[CHUNK_];
    s[i] = dA;
    __syncthreads();
    for (int off = 1; off < CHUNK_; off <<= 1) {
        float tv = (i >= off) ? s[i - off] : 0.f;
        __syncthreads();
        s[i] += tv;
        __syncthreads();
    }
    float cs = s[i], cl = s[CHUNK_ - 1];
    size_t basei = ((size_t)bb * NH + h) * LSEQ + t;
    g_E[basei]    = expf(cs);
    g_Binv[basei] = ds * expf(-cs);
    g_Wst[basei]  = ds * expf(cl - cs);
    if (i == 0) g_cd[(bb * NCH + c) * NH + h] = expf(cl);
}

// ---------------- transpose x -> Xt [bb][d][t] ----------------
__global__ void k_xt(const float* __restrict__ x) {
    int bb = blockIdx.z;
    int tB = blockIdx.x * 32, dB = blockIdx.y * 32;
    __shared__ float s[32][33];
    int lr = threadIdx.x >> 5, lc = threadIdx.x & 31;
#pragma unroll
    for (int j = 0; j < 4; j++)
        s[lr + j * 8][lc] = x[src_row(bb, tB + lr + j * 8) * DIN + dB + lc];
    __syncthreads();
#pragma unroll
    for (int j = 0; j < 4; j++)
        g_Xt[((size_t)bb * DIN + dB + lr + j * 8) * LSEQ + tB + lc] = s[lc][lr + j * 8];
}

// ---------------- transpose B -> Bt [z][n][k] ----------------
__global__ void k_bt(const float* __restrict__ BC) {
    int z = blockIdx.z;
    int c = z % NCH, bb = z / NCH;
    int kB = blockIdx.x * 32, nB = blockIdx.y * 32;
    __shared__ float s[32][33];
    int lr = threadIdx.x >> 5, lc = threadIdx.x & 31;
#pragma unroll
    for (int j = 0; j < 4; j++)
        s[lr + j * 8][lc] = BC[src_row(bb, c * CHUNK_ + kB + lr + j * 8) * (2 * NSTATE) + nB + lc];
    __syncthreads();
#pragma unroll
    for (int j = 0; j < 4; j++)
        g_Bt[((size_t)z * NSTATE + nB + lr + j * 8) * CHUNK_ + kB + lc] = s[lc][lr + j * 8];
}

// ---------------- CB GEMM: g_CB[z][i][k] = sum_n C[i,n] B[k,n] ----------------
__global__ void __launch_bounds__(256) k_cb(const float* __restrict__ BC) {
    int iT = blockIdx.x, kT = blockIdx.y, z = blockIdx.z;
    if (iT == 0 && kT == 1) return;   // fully masked tile, never read
    int c = z % NCH, bb = z / NCH;
    auto lA = [&](int row, int col, float* v) {
        const float* p = BC + src_row(bb, c * CHUNK_ + iT * 128 + row) * (2 * NSTATE) + NSTATE + col;
#pragma unroll
        for (int j = 0; j < 16; j += 4) *(float4*)&v[j] = *(const float4*)&p[j];
    };
    auto lB = [&](int row, int col, float* v) {
        const float* p = BC + src_row(bb, c * CHUNK_ + kT * 128 + row) * (2 * NSTATE) + col;
#pragma unroll
        for (int j = 0; j < 16; j += 4) *(float4*)&v[j] = *(const float4*)&p[j];
    };
    gemm128(NSTATE / 32, lA, lB,
            g_CB + ((size_t)z * CHUNK_ + iT * 128) * CHUNK_ + kT * 128, CHUNK_);
}

// ---------------- states GEMM: g_S[z][h][p][n] = sum_k Xt[p,k] (w_k Bt[n,k]) ----------------
__global__ void __launch_bounds__(256) k_states() {
    int nT = blockIdx.x, h = blockIdx.y, z = blockIdx.z;
    int c = z % NCH, bb = z / NCH;
    auto lA = [&](int row, int col, float* v) {
        const float* p = g_Xt + ((size_t)(bb * NH + h) * HD + row) * LSEQ + c * CHUNK_ + col;
#pragma unroll
        for (int j = 0; j < 16; j += 4) *(float4*)&v[j] = *(const float4*)&p[j];
    };
    auto lB = [&](int row, int col, float* v) {
        const float* p = g_Bt + ((size_t)z * NSTATE + nT * 128 + row) * CHUNK_ + col;
        const float* w = g_Wst + (size_t)(bb * NH + h) * LSEQ + c * CHUNK_ + col;
#pragma unroll
        for (int j = 0; j < 16; j++) v[j] = p[j] * w[j];
    };
    gemm128(CHUNK_ / 32, lA, lB,
            g_S + (size_t)(z * NH + h) * HD * NSTATE + nT * 128, NSTATE);
}

// ---------------- inter-chunk scan (in place on g_S) ----------------
__global__ void k_scan() {
    int idx = blockIdx.x * blockDim.x + threadIdx.x;
    int n = idx & (NSTATE - 1);
    int p = (idx >> 8) & (HD - 1);
    int h = (idx >> 15) & (NH - 1);
    int bb = idx >> 19;
    size_t rest = ((size_t)h * HD + p) * NSTATE + n;
    const size_t stride = (size_t)NH * HD * NSTATE;
    float carry = 0.f;
    for (int c = 0; c < NCH; c++) {
        size_t off = (size_t)(bb * NCH + c) * stride + rest;
        float sv = g_S[off];
        g_S[off] = carry;
        carry = carry * g_cd[(bb * NCH + c) * NH + h] + sv;
    }
}

// ---------------- y GEMM: ybuf[t][p] = (CB*binv*mask) @ X  +  C @ prev ----------------
__global__ void __launch_bounds__(256) k_y(const float* __restrict__ BC) {
    int iT = blockIdx.x, h = blockIdx.y, z = blockIdx.z;
    int c = z % NCH, bb = z / NCH;
    const int p0len = (iT ? 256 : 128);       // phase-0 K extent (k <= i only)
    const int nkb = p0len / 32 + NSTATE / 32;
    auto lA = [&](int row, int col, float* v) {
        int i_g = iT * 128 + row;
        if (col < p0len) {
            const float* pcb = g_CB + ((size_t)z * CHUNK_ + i_g) * CHUNK_ + col;
            const float* pbv = g_Binv + (size_t)(bb * NH + h) * LSEQ + c * CHUNK_ + col;
#pragma unroll
            for (int j = 0; j < 16; j++) v[j] = (col + j <= i_g) ? pcb[j] * pbv[j] : 0.f;
        } else {
            int n = col - p0len;
            const float* p = BC + src_row(bb, c * CHUNK_ + i_g) * (2 * NSTATE) + NSTATE + n;
#pragma unroll
            for (int j = 0; j < 16; j += 4) *(float4*)&v[j] = *(const float4*)&p[j];
        }
    };
    auto lB = [&](int row, int col, float* v) {
        const float* p;
        if (col < p0len)
            p = g_Xt + ((size_t)(bb * NH + h) * HD + row) * LSEQ + c * CHUNK_ + col;
        else
            p = g_S + ((size_t)(z * NH + h) * HD + row) * NSTATE + (col - p0len);
#pragma unroll
        for (int j = 0; j < 16; j += 4) *(float4*)&v[j] = *(const float4*)&p[j];
    };
    gemm128(nkb, lA, lB,
            g_ybuf + ((size_t)(bb * NH + h) * LSEQ + c * CHUNK_ + iT * 128) * HD, HD);
}

// ---------------- final combine (applies e-scale to rolled y terms) ----------------
__global__ void k_final(const float* __restrict__ x, const float* __restrict__ W,
                        const float* __restrict__ Dp, float* __restrict__ out) {
    int t = blockIdx.x, b = blockIdx.y;
    __shared__ float xs[DIN];
    __shared__ float gate[NH];
    const float* xrow = x + ((size_t)b * LSEQ + t) * DIN;
    for (int d = threadIdx.x; d < DIN; d += 256) xs[d] = xrow[d];
    __syncthreads();
    int warp = threadIdx.x / 32, lane = threadIdx.x % 32;
#pragma unroll
    for (int hh = 0; hh < 2; hh++) {
        int h = warp * 2 + hh;
        const float* wrow = W + (size_t)h * DIN;
        float acc = 0.f;
        for (int d = lane; d < DIN; d += 32) acc += xs[d] * wrow[d];
#pragma unroll
        for (int o = 16; o; o >>= 1) acc += __shfl_down_sync(0xFFFFFFFFu, acc, o);
        if (lane == 0) gate[h] = acc + Dp[h];
    }
    __syncthreads();
    int tb = LSEQ - 1 - t;
    float* orow = out + ((size_t)b * LSEQ + t) * DIN;
    for (int d = threadIdx.x; d < DIN; d += 256) {
        int h = d >> 7, p = d & 127;
        float v = xs[d] * gate[h];
        if (t > 0) {
            size_t idx = (size_t)(b * NH + h) * LSEQ + (t - 1);
            v += g_ybuf[idx * HD + p] * g_E[idx];
        }
        if (tb > 0) {
            size_t idx = (size_t)((b + 2) * NH + h) * LSEQ + (tb - 1);
            v += g_ybuf[idx * HD + p] * g_E[idx];
        }
        orow[d] = v;
    }
}

// ---------------- launch ----------------
extern "C" void kernel_launch(void* const* d_in, const int* in_sizes, int n_in,
                              void* d_out, int out_size) {
    const float* x     = (const float*)d_in[0];
    const float* BC    = (const float*)d_in[1];
    const float* dt    = (const float*)d_in[2];
    const float* A_log = (const float*)d_in[3];
    const float* Dv    = (const float*)d_in[4];
    const float* W     = (const float*)d_in[5];
    float* out = (float*)d_out;

    k_pre   <<<dim3(NCH, NH, NBB), 256>>>(dt, A_log);
    k_xt    <<<dim3(LSEQ / 32, DIN / 32, NBB), 256>>>(x);
    k_bt    <<<dim3(8, 8, ZTOT), 256>>>(BC);
    k_cb    <<<dim3(2, 2, ZTOT), 256>>>(BC);
    k_states<<<dim3(2, NH, ZTOT), 256>>>();
    k_scan  <<<(NBB * NH * HD * NSTATE) / 256, 256>>>();
    k_y     <<<dim3(2, NH, ZTOT), 256>>>(BC);
    k_final <<<dim3(LSEQ, BSZ), 256>>>(x, W, Dv, out);
}

// round 5
// speedup vs baseline: 2.5223x; 2.3100x over previous
#include <cuda_runtime.h>
#include <cuda_bf16.h>
#include <mma.h>
#include <math.h>
#include <stdint.h>

using namespace nvcuda;

#define BSZ    2
#define LSEQ   4096
#define NH     16
#define HD     128
#define NSTATE 256
#define CHUNK_ 256
#define NCH    16
#define NBB    4
#define DIN    2048
#define ZTOT   64

typedef __nv_bfloat16 bf16;

// ---------------- static device scratch ----------------
__device__ float g_E   [(size_t)NBB*NH*LSEQ];
__device__ float g_Binv[(size_t)NBB*NH*LSEQ];
__device__ float g_Wst [(size_t)NBB*NH*LSEQ];
__device__ float g_cd  [ZTOT*NH];
__device__ __align__(16) bf16 g_BCh[(size_t)BSZ*LSEQ*2*NSTATE];  // BC hi  [b][t][512]
__device__ __align__(16) bf16 g_BCl[(size_t)BSZ*LSEQ*2*NSTATE];  // BC lo
__device__ __align__(16) bf16 g_XWh[(size_t)NBB*DIN*LSEQ];       // w*x^T hi [bb][d][t]
__device__ __align__(16) bf16 g_XWl[(size_t)NBB*DIN*LSEQ];
__device__ __align__(16) bf16 g_XBh[(size_t)NBB*DIN*LSEQ];       // binv*x^T hi
__device__ __align__(16) bf16 g_XBl[(size_t)NBB*DIN*LSEQ];
__device__ __align__(16) bf16 g_Bth[(size_t)ZTOT*NSTATE*CHUNK_]; // B^T hi [z][n][k]
__device__ __align__(16) bf16 g_Btl[(size_t)ZTOT*NSTATE*CHUNK_];
__device__ float g_CB  [(size_t)ZTOT*CHUNK_*CHUNK_];             // fp32 CB (unmasked)
__device__ __align__(16) bf16 g_CBh[(size_t)ZTOT*CHUNK_*CHUNK_]; // masked CB hi [z][i][k]
__device__ __align__(16) bf16 g_CBl[(size_t)ZTOT*CHUNK_*CHUNK_];
__device__ float g_S   [(size_t)ZTOT*NH*HD*NSTATE];              // [z][h][p][n]
__device__ __align__(16) bf16 g_Ph [(size_t)ZTOT*NH*HD*NSTATE];  // prev hi
__device__ __align__(16) bf16 g_Pl [(size_t)ZTOT*NH*HD*NSTATE];  // prev lo
__device__ float g_ybuf[(size_t)NBB*NH*LSEQ*HD];                 // [bb][h][t][p]

__device__ __forceinline__ size_t src_row(int bb, int t) {
    return (size_t)(bb & 1) * LSEQ + (size_t)(bb < 2 ? t : (LSEQ - 1 - t));
}
__device__ __forceinline__ void bsplit(float v, bf16& h, bf16& l) {
    h = __float2bfloat16(v);
    l = __float2bfloat16(v - __bfloat162float(h));
}
__device__ __forceinline__ uint32_t smem_u32(const void* p) {
    uint32_t a;
    asm("{ .reg .u64 t; cvta.to.shared.u64 t, %1; cvt.u32.u64 %0, t; }" : "=r"(a) : "l"(p));
    return a;
}
__device__ __forceinline__ void cpa16(uint32_t s, const void* g) {
    asm volatile("cp.async.ca.shared.global [%0], [%1], 16;" :: "r"(s), "l"(g));
}

// ---------------- generic 128x128 bf16-pair GEMM, cp.async double-buffered ----------------
// src(tile, row, kb) -> pointer to 32 contiguous bf16. tile: 0=Ah 1=Al 2=Bh 3=Bl.
#define TILE_E (128*40)
#define BUF_E  (4*TILE_E)
#define SMEM_B (2*BUF_E*2)

template <typename SRC>
__device__ __forceinline__ void gemm128(int nkb, SRC src, float* out, int ldOut) {
    extern __shared__ __align__(16) bf16 sm[];
    const int tid = threadIdx.x;
    const int warp = tid >> 5, wr = warp >> 1, wc = warp & 1;
    const int r0 = tid & 127, t0 = tid >> 7;
    const uint32_t sbase = smem_u32(sm);

    wmma::fragment<wmma::accumulator, 16, 16, 16, float> acc[2][4];
#pragma unroll
    for (int i = 0; i < 2; i++)
#pragma unroll
        for (int j = 0; j < 4; j++) wmma::fill_fragment(acc[i][j], 0.0f);

    auto stage = [&](int kb, int buf) {
#pragma unroll
        for (int rep = 0; rep < 2; rep++) {
            int tile = t0 + rep * 2;
            const bf16* g = src(tile, r0, kb);
            uint32_t s = sbase + (uint32_t)(buf * BUF_E + tile * TILE_E + r0 * 40) * 2;
            cpa16(s, g); cpa16(s + 16, g + 8); cpa16(s + 32, g + 16); cpa16(s + 48, g + 24);
        }
        asm volatile("cp.async.commit_group;" ::: "memory");
    };

    stage(0, 0);
    for (int kb = 0; kb < nkb; kb++) {
        int buf = kb & 1;
        if (kb + 1 < nkb) {
            stage(kb + 1, buf ^ 1);
            asm volatile("cp.async.wait_group 1;" ::: "memory");
        } else {
            asm volatile("cp.async.wait_group 0;" ::: "memory");
        }
        __syncthreads();
        const bf16* base = sm + buf * BUF_E;
#pragma unroll
        for (int ks = 0; ks < 32; ks += 16) {
#pragma unroll
            for (int pass = 0; pass < 3; pass++) {
                const bf16* SA = base + ((pass == 2) ? TILE_E : 0);
                const bf16* SB = base + 2 * TILE_E + ((pass == 1) ? TILE_E : 0);
                wmma::fragment<wmma::matrix_a, 16, 16, 16, bf16, wmma::row_major> af[2];
                wmma::load_matrix_sync(af[0], SA + (wr * 32) * 40 + ks, 40);
                wmma::load_matrix_sync(af[1], SA + (wr * 32 + 16) * 40 + ks, 40);
                wmma::fragment<wmma::matrix_b, 16, 16, 16, bf16, wmma::col_major> bf[4];
#pragma unroll
                for (int j = 0; j < 4; j++)
                    wmma::load_matrix_sync(bf[j], SB + (wc * 64 + j * 16) * 40 + ks, 40);
#pragma unroll
                for (int i = 0; i < 2; i++)
#pragma unroll
                    for (int j = 0; j < 4; j++)
                        wmma::mma_sync(acc[i][j], af[i], bf[j], acc[i][j]);
            }
        }
        __syncthreads();
    }
#pragma unroll
    for (int i = 0; i < 2; i++)
#pragma unroll
        for (int j = 0; j < 4; j++)
            wmma::store_matrix_sync(out + (size_t)(wr * 32 + i * 16) * ldOut + wc * 64 + j * 16,
                                    acc[i][j], ldOut, wmma::mem_row_major);
}

// ---------------- K1: softplus, cumsum, exp factors ----------------
__global__ void k_pre(const float* __restrict__ dt, const float* __restrict__ A_log) {
    int c = blockIdx.x, h = blockIdx.y, bb = blockIdx.z;
    int i = threadIdx.x;
    int t = c * CHUNK_ + i;
    int trow = (bb < 2) ? t : (LSEQ - 1 - t);
    int ch   = (bb < 2) ? h : (h + NH);
    float dtv = dt[((size_t)(bb & 1) * LSEQ + trow) * (2 * NH) + ch];
    float ds  = (dtv > 20.f) ? dtv : log1pf(expf(dtv));
    float dA  = ds * (-expf(A_log[h]));
    __shared__ float s[CHUNK_];
    s[i] = dA;
    __syncthreads();
    for (int off = 1; off < CHUNK_; off <<= 1) {
        float tv = (i >= off) ? s[i - off] : 0.f;
        __syncthreads();
        s[i] += tv;
        __syncthreads();
    }
    float cs = s[i], cl = s[CHUNK_ - 1];
    size_t basei = ((size_t)bb * NH + h) * LSEQ + t;
    g_E[basei]    = expf(cs);
    g_Binv[basei] = ds * expf(-cs);
    g_Wst[basei]  = ds * expf(cl - cs);
    if (i == 0) g_cd[(bb * NCH + c) * NH + h] = expf(cl);
}

// ---------------- split BC -> bf16 hi/lo [b][t][512] ----------------
__global__ void k_split_bc(const float* __restrict__ BC) {
    size_t row = blockIdx.x + (size_t)blockIdx.y * LSEQ;
    int col = threadIdx.x * 4;
    const float* p = BC + row * (2 * NSTATE) + col;
    float4 v = *(const float4*)p;
    bf16 h0, l0, h1, l1, h2, l2, h3, l3;
    bsplit(v.x, h0, l0); bsplit(v.y, h1, l1); bsplit(v.z, h2, l2); bsplit(v.w, h3, l3);
    size_t o = row * (2 * NSTATE) + col;
    g_BCh[o] = h0; g_BCh[o+1] = h1; g_BCh[o+2] = h2; g_BCh[o+3] = h3;
    g_BCl[o] = l0; g_BCl[o+1] = l1; g_BCl[o+2] = l2; g_BCl[o+3] = l3;
}

// ---------------- transpose + scale + split x -> XW/XB pairs [bb][d][t] ----------------
__global__ void k_xsplit(const float* __restrict__ x) {
    int bb = blockIdx.z;
    int tB = blockIdx.x * 32, dB = blockIdx.y * 32;
    __shared__ float s[32][33];
    int lr = threadIdx.x >> 5, lc = threadIdx.x & 31;
#pragma unroll
    for (int j = 0; j < 4; j++)
        s[lr + j * 8][lc] = x[src_row(bb, tB + lr + j * 8) * DIN + dB + lc];
    __syncthreads();
    int t = tB + lc;
#pragma unroll
    for (int j = 0; j < 4; j++) {
        int d = dB + lr + j * 8;
        int h = d >> 7;
        float v = s[lc][lr + j * 8];
        size_t si = ((size_t)bb * NH + h) * LSEQ + t;
        size_t oi = ((size_t)bb * DIN + d) * LSEQ + t;
        bf16 hh, ll;
        bsplit(v * g_Wst[si], hh, ll);
        g_XWh[oi] = hh; g_XWl[oi] = ll;
        bsplit(v * g_Binv[si], hh, ll);
        g_XBh[oi] = hh; g_XBl[oi] = ll;
    }
}

// ---------------- transpose + split B -> Bt pairs [z][n][k] ----------------
__global__ void k_btsplit(const float* __restrict__ BC) {
    int z = blockIdx.z;
    int c = z % NCH, bb = z / NCH;
    int kB = blockIdx.x * 32, nB = blockIdx.y * 32;
    __shared__ float s[32][33];
    int lr = threadIdx.x >> 5, lc = threadIdx.x & 31;
#pragma unroll
    for (int j = 0; j < 4; j++)
        s[lr + j * 8][lc] = BC[src_row(bb, c * CHUNK_ + kB + lr + j * 8) * (2 * NSTATE) + nB + lc];
    __syncthreads();
#pragma unroll
    for (int j = 0; j < 4; j++) {
        int n = nB + lr + j * 8;
        size_t oi = ((size_t)z * NSTATE + n) * CHUNK_ + kB + lc;
        bf16 hh, ll;
        bsplit(s[lc][lr + j * 8], hh, ll);
        g_Bth[oi] = hh; g_Btl[oi] = ll;
    }
}

// ---------------- CB GEMM: g_CB[z][i][k] = sum_n C[i,n] B[k,n] ----------------
__global__ void __launch_bounds__(256, 2) k_cb() {
    int iT = blockIdx.x, kT = blockIdx.y, z = blockIdx.z;
    if (iT == 0 && kT == 1) return;
    int c = z % NCH, bb = z / NCH;
    auto src = [&](int tile, int row, int kb) -> const bf16* {
        const bf16* arr = (tile & 1) ? g_BCl : g_BCh;
        if (tile < 2)
            return arr + src_row(bb, c * CHUNK_ + iT * 128 + row) * (2 * NSTATE) + NSTATE + kb * 32;
        return arr + src_row(bb, c * CHUNK_ + kT * 128 + row) * (2 * NSTATE) + kb * 32;
    };
    gemm128(NSTATE / 32, src, g_CB + ((size_t)z * CHUNK_ + iT * 128) * CHUNK_ + kT * 128, CHUNK_);
}

// ---------------- mask + split CB ----------------
__global__ void k_cbsplit() {
    int i = blockIdx.x, z = blockIdx.y;
    int k = threadIdx.x;
    size_t o = ((size_t)z * CHUNK_ + i) * CHUNK_ + k;
    float v = (k <= i) ? g_CB[o] : 0.f;
    bf16 hh, ll;
    bsplit(v, hh, ll);
    g_CBh[o] = hh; g_CBl[o] = ll;
}

// ---------------- states GEMM: g_S[z][h][p][n] = sum_k XW[p,k] Bt[n,k] ----------------
__global__ void __launch_bounds__(256, 2) k_states() {
    int nT = blockIdx.x, h = blockIdx.y, z = blockIdx.z;
    int c = z % NCH, bb = z / NCH;
    auto src = [&](int tile, int row, int kb) -> const bf16* {
        if (tile < 2) {
            const bf16* arr = (tile & 1) ? g_XWl : g_XWh;
            return arr + ((size_t)bb * DIN + h * 128 + row) * LSEQ + c * CHUNK_ + kb * 32;
        }
        const bf16* arr = (tile & 1) ? g_Btl : g_Bth;
        return arr + ((size_t)z * NSTATE + nT * 128 + row) * CHUNK_ + kb * 32;
    };
    gemm128(CHUNK_ / 32, src, g_S + (size_t)(z * NH + h) * HD * NSTATE + nT * 128, NSTATE);
}

// ---------------- inter-chunk scan: g_S -> prev pairs ----------------
__global__ void k_scan() {
    int idx = blockIdx.x * blockDim.x + threadIdx.x;
    int n = idx & (NSTATE - 1);
    int p = (idx >> 8) & (HD - 1);
    int h = (idx >> 15) & (NH - 1);
    int bb = idx >> 19;
    size_t rest = ((size_t)h * HD + p) * NSTATE + n;
    const size_t stride = (size_t)NH * HD * NSTATE;
    float carry = 0.f;
    for (int c = 0; c < NCH; c++) {
        size_t off = (size_t)(bb * NCH + c) * stride + rest;
        float sv = g_S[off];
        bf16 hh, ll;
        bsplit(carry, hh, ll);
        g_Ph[off] = hh; g_Pl[off] = ll;
        carry = carry * g_cd[(bb * NCH + c) * NH + h] + sv;
    }
}

// ---------------- y GEMM: ybuf[t][p] = CBm @ XB + C @ prev ----------------
__global__ void __launch_bounds__(256, 2) k_y() {
    int iT = blockIdx.x, h = blockIdx.y, z = blockIdx.z;
    int c = z % NCH, bb = z / NCH;
    const int p0kb = (iT ? 8 : 4);
    auto src = [&](int tile, int row, int kb) -> const bf16* {
        if (kb < p0kb) {
            if (tile < 2) {
                const bf16* arr = (tile & 1) ? g_CBl : g_CBh;
                return arr + ((size_t)z * CHUNK_ + iT * 128 + row) * CHUNK_ + kb * 32;
            }
            const bf16* arr = (tile & 1) ? g_XBl : g_XBh;
            return arr + ((size_t)bb * DIN + h * 128 + row) * LSEQ + c * CHUNK_ + kb * 32;
        }
        int n0 = (kb - p0kb) * 32;
        if (tile < 2) {
            const bf16* arr = (tile & 1) ? g_BCl : g_BCh;
            return arr + src_row(bb, c * CHUNK_ + iT * 128 + row) * (2 * NSTATE) + NSTATE + n0;
        }
        const bf16* arr = (tile & 1) ? g_Pl : g_Ph;
        return arr + ((size_t)(z * NH + h) * HD + row) * NSTATE + n0;
    };
    gemm128(p0kb + NSTATE / 32, src,
            g_ybuf + ((size_t)(bb * NH + h) * LSEQ + c * CHUNK_ + iT * 128) * HD, HD);
}

// ---------------- final combine ----------------
__global__ void k_final(const float* __restrict__ x, const float* __restrict__ W,
                        const float* __restrict__ Dp, float* __restrict__ out) {
    int t = blockIdx.x, b = blockIdx.y;
    __shared__ float xs[DIN];
    __shared__ float gate[NH];
    const float* xrow = x + ((size_t)b * LSEQ + t) * DIN;
    for (int d = threadIdx.x; d < DIN; d += 256) xs[d] = xrow[d];
    __syncthreads();
    int warp = threadIdx.x / 32, lane = threadIdx.x % 32;
#pragma unroll
    for (int hh = 0; hh < 2; hh++) {
        int h = warp * 2 + hh;
        const float* wrow = W + (size_t)h * DIN;
        float acc = 0.f;
        for (int d = lane; d < DIN; d += 32) acc += xs[d] * wrow[d];
#pragma unroll
        for (int o = 16; o; o >>= 1) acc += __shfl_down_sync(0xFFFFFFFFu, acc, o);
        if (lane == 0) gate[h] = acc + Dp[h];
    }
    __syncthreads();
    int tb = LSEQ - 1 - t;
    float* orow = out + ((size_t)b * LSEQ + t) * DIN;
    for (int d = threadIdx.x; d < DIN; d += 256) {
        int h = d >> 7, p = d & 127;
        float v = xs[d] * gate[h];
        if (t > 0) {
            size_t idx = (size_t)(b * NH + h) * LSEQ + (t - 1);
            v += g_ybuf[idx * HD + p] * g_E[idx];
        }
        if (tb > 0) {
            size_t idx = (size_t)((b + 2) * NH + h) * LSEQ + (tb - 1);
            v += g_ybuf[idx * HD + p] * g_E[idx];
        }
        orow[d] = v;
    }
}

// ---------------- launch ----------------
extern "C" void kernel_launch(void* const* d_in, const int* in_sizes, int n_in,
                              void* d_out, int out_size) {
    const float* x     = (const float*)d_in[0];
    const float* BC    = (const float*)d_in[1];
    const float* dt    = (const float*)d_in[2];
    const float* A_log = (const float*)d_in[3];
    const float* Dv    = (const float*)d_in[4];
    const float* W     = (const float*)d_in[5];
    float* out = (float*)d_out;

    static int inited = 0;
    if (!inited) {
        cudaFuncSetAttribute(k_cb,     cudaFuncAttributeMaxDynamicSharedMemorySize, SMEM_B);
        cudaFuncSetAttribute(k_states, cudaFuncAttributeMaxDynamicSharedMemorySize, SMEM_B);
        cudaFuncSetAttribute(k_y,      cudaFuncAttributeMaxDynamicSharedMemorySize, SMEM_B);
        inited = 1;
    }

    k_pre     <<<dim3(NCH, NH, NBB), 256>>>(dt, A_log);
    k_split_bc<<<dim3(LSEQ, BSZ), 128>>>(BC);
    k_xsplit  <<<dim3(LSEQ / 32, DIN / 32, NBB), 256>>>(x);
    k_btsplit <<<dim3(8, 8, ZTOT), 256>>>(BC);
    k_cb      <<<dim3(2, 2, ZTOT), 256, SMEM_B>>>();
    k_cbsplit <<<dim3(CHUNK_, ZTOT), 256>>>();
    k_states  <<<dim3(2, NH, ZTOT), 256, SMEM_B>>>();
    k_scan    <<<(NBB * NH * HD * NSTATE) / 256, 256>>>();
    k_y       <<<dim3(2, NH, ZTOT), 256, SMEM_B>>>();
    k_final   <<<dim3(LSEQ, BSZ), 256>>>(x, W, Dv, out);
}

// round 6
// speedup vs baseline: 3.9299x; 1.5581x over previous
#include <cuda_runtime.h>
#include <cuda_fp16.h>
#include <mma.h>
#include <math.h>
#include <stdint.h>

using namespace nvcuda;

#define BSZ    2
#define LSEQ   4096
#define NH     16
#define HD     128
#define NSTATE 256
#define CHUNK_ 256
#define NCH    16
#define NBB    4
#define DIN    2048
#define ZTOT   64

typedef __half hf;

// ---------------- static device scratch ----------------
__device__ float g_E2 [(size_t)NBB*NH*LSEQ];   // exp(cs_i - m(tile(i)))
__device__ float g_Wst[(size_t)NBB*NH*LSEQ];   // dt * exp(cs_last - cs)
__device__ float g_W0 [(size_t)NBB*NH*LSEQ];   // dt * exp(m0 - cs)
__device__ float g_W1 [(size_t)NBB*NH*LSEQ];   // dt * exp(m1 - cs)
__device__ float g_PS [ZTOT*NH*2];             // exp(m0), exp(m1)
__device__ float g_cd [ZTOT*NH];               // exp(cs_last)
__device__ __align__(16) hf g_BCf[(size_t)BSZ*LSEQ*2*NSTATE];   // BC fp16 [b][t][512]
__device__ __align__(16) hf g_XW [(size_t)NBB*DIN*LSEQ];        // wst*x^T  [bb][d][t]
__device__ __align__(16) hf g_XB1[(size_t)NBB*DIN*LSEQ];        // w1*x^T   [bb][d][t]
__device__ __align__(16) hf g_XB0[(size_t)NBB*DIN*LSEQ/2];      // w0*x^T   [bb][d][c][128] (k<128 only)
__device__ __align__(16) hf g_Btf[(size_t)ZTOT*NSTATE*CHUNK_];  // B^T fp16 [z][n][k]
__device__ float g_CB [(size_t)ZTOT*CHUNK_*CHUNK_];             // fp32 CB (unmasked)
__device__ __align__(16) hf g_CBf[(size_t)ZTOT*CHUNK_*CHUNK_];  // masked CB fp16 [z][i][k]
__device__ float g_S  [(size_t)ZTOT*NH*HD*NSTATE];              // states fp32 [z][h][p][n]
__device__ __align__(16) hf g_P0 [(size_t)ZTOT*NH*HD*NSTATE];   // prev*exp(m0) fp16
__device__ __align__(16) hf g_P1 [(size_t)ZTOT*NH*HD*NSTATE];   // prev*exp(m1) fp16
__device__ __align__(16) hf g_ybuf[(size_t)NBB*NH*LSEQ*HD];     // y fp16 [bb][h][t][p] (e2-scaled)

__device__ __forceinline__ size_t src_row(int bb, int t) {
    return (size_t)(bb & 1) * LSEQ + (size_t)(bb < 2 ? t : (LSEQ - 1 - t));
}
__device__ __forceinline__ uint32_t smem_u32(const void* p) {
    uint32_t a;
    asm("{ .reg .u64 t; cvta.to.shared.u64 t, %1; cvt.u32.u64 %0, t; }" : "=r"(a) : "l"(p));
    return a;
}
__device__ __forceinline__ void cpa16(uint32_t s, const void* g) {
    asm volatile("cp.async.ca.shared.global [%0], [%1], 16;" :: "r"(s), "l"(g));
}

// ---------------- generic 128x128 fp16 GEMM, 3-stage cp.async pipeline ----------------
// src(tile 0=A / 1=B, row 0..127, kb) -> pointer to 32 contiguous halfs.
#define TILE_E  (128*40)
#define NSTAGE  3
#define SMEM_GG (NSTAGE*2*TILE_E*2)       // 61440 bytes
#define SMEM_YY 65536                     // epilogue fp32 staging (>= SMEM_GG)

template <bool HOUT, typename SRC>
__device__ __forceinline__ void gemm128(int nkb, SRC src, void* outp, int ldOut,
                                        const float* escale) {
    extern __shared__ __align__(16) hf sm[];
    const int tid = threadIdx.x;
    const int warp = tid >> 5, wr = warp >> 1, wc = warp & 1;
    const int r0 = tid & 127, t0 = tid >> 7;
    const uint32_t sbase = smem_u32(sm);

    wmma::fragment<wmma::accumulator, 16, 16, 16, float> acc[2][4];
#pragma unroll
    for (int i = 0; i < 2; i++)
#pragma unroll
        for (int j = 0; j < 4; j++) wmma::fill_fragment(acc[i][j], 0.0f);

    auto stage = [&](int kb) {
        if (kb < nkb) {
            int s = kb % NSTAGE;
            const hf* g = src(t0, r0, kb);
            uint32_t sa = sbase + (uint32_t)((s * 2 + t0) * TILE_E + r0 * 40) * 2;
            cpa16(sa, g); cpa16(sa + 16, g + 8); cpa16(sa + 32, g + 16); cpa16(sa + 48, g + 24);
        }
        asm volatile("cp.async.commit_group;" ::: "memory");
    };

    stage(0); stage(1);
    for (int kb = 0; kb < nkb; kb++) {
        stage(kb + 2);
        asm volatile("cp.async.wait_group 2;" ::: "memory");
        __syncthreads();
        const hf* base = sm + (kb % NSTAGE) * 2 * TILE_E;
#pragma unroll
        for (int ks = 0; ks < 32; ks += 16) {
            wmma::fragment<wmma::matrix_a, 16, 16, 16, hf, wmma::row_major> af[2];
            wmma::load_matrix_sync(af[0], base + (wr * 32) * 40 + ks, 40);
            wmma::load_matrix_sync(af[1], base + (wr * 32 + 16) * 40 + ks, 40);
            wmma::fragment<wmma::matrix_b, 16, 16, 16, hf, wmma::col_major> bf[4];
#pragma unroll
            for (int j = 0; j < 4; j++)
                wmma::load_matrix_sync(bf[j], base + TILE_E + (wc * 64 + j * 16) * 40 + ks, 40);
#pragma unroll
            for (int i = 0; i < 2; i++)
#pragma unroll
                for (int j = 0; j < 4; j++)
                    wmma::mma_sync(acc[i][j], af[i], bf[j], acc[i][j]);
        }
        __syncthreads();
    }

    if (HOUT) {
        float* smf = (float*)sm;
#pragma unroll
        for (int i = 0; i < 2; i++)
#pragma unroll
            for (int j = 0; j < 4; j++)
                wmma::store_matrix_sync(smf + (size_t)(wr * 32 + i * 16) * 128 + wc * 64 + j * 16,
                                        acc[i][j], 128, wmma::mem_row_major);
        __syncthreads();
        float e = escale[r0];
        hf* orow = (hf*)outp + (size_t)r0 * ldOut + t0 * 64;
        const float* srow = smf + (size_t)r0 * 128 + t0 * 64;
#pragma unroll
        for (int j = 0; j < 64; j += 8) {
            hf tmp[8];
#pragma unroll
            for (int u = 0; u < 8; u++) tmp[u] = __float2half_rn(srow[j + u] * e);
            *(uint4*)&orow[j] = *(uint4*)tmp;
        }
    } else {
#pragma unroll
        for (int i = 0; i < 2; i++)
#pragma unroll
            for (int j = 0; j < 4; j++)
                wmma::store_matrix_sync((float*)outp + (size_t)(wr * 32 + i * 16) * ldOut + wc * 64 + j * 16,
                                        acc[i][j], ldOut, wmma::mem_row_major);
    }
}

// ---------------- K1: softplus, cumsum, exp factors ----------------
__global__ void k_pre(const float* __restrict__ dt, const float* __restrict__ A_log) {
    int c = blockIdx.x, h = blockIdx.y, bb = blockIdx.z;
    int i = threadIdx.x;
    int t = c * CHUNK_ + i;
    int trow = (bb < 2) ? t : (LSEQ - 1 - t);
    int ch   = (bb < 2) ? h : (h + NH);
    float dtv = dt[((size_t)(bb & 1) * LSEQ + trow) * (2 * NH) + ch];
    float ds  = (dtv > 20.f) ? dtv : log1pf(expf(dtv));
    float dA  = ds * (-expf(A_log[h]));
    __shared__ float s[CHUNK_];
    s[i] = dA;
    __syncthreads();
    for (int off = 1; off < CHUNK_; off <<= 1) {
        float tv = (i >= off) ? s[i - off] : 0.f;
        __syncthreads();
        s[i] += tv;
        __syncthreads();
    }
    float cs = s[i], cl = s[CHUNK_ - 1];
    float m0 = s[64], m1 = s[192];
    size_t basei = ((size_t)bb * NH + h) * LSEQ + t;
    g_E2 [basei] = expf(cs - ((i < 128) ? m0 : m1));
    g_Wst[basei] = ds * expf(cl - cs);
    g_W0 [basei] = ds * expf(m0 - cs);
    g_W1 [basei] = ds * expf(m1 - cs);
    if (i == 0) {
        int zh = (bb * NCH + c) * NH + h;
        g_cd[zh] = expf(cl);
        g_PS[zh * 2]     = expf(m0);
        g_PS[zh * 2 + 1] = expf(m1);
    }
}

// ---------------- split BC -> fp16 [b][t][512] ----------------
__global__ void k_split_bc(const float* __restrict__ BC) {
    size_t row = blockIdx.x + (size_t)blockIdx.y * LSEQ;
    int col = threadIdx.x * 4;
    float4 v = *(const float4*)(BC + row * (2 * NSTATE) + col);
    hf tmp[4] = {__float2half_rn(v.x), __float2half_rn(v.y),
                 __float2half_rn(v.z), __float2half_rn(v.w)};
    *(uint2*)&g_BCf[row * (2 * NSTATE) + col] = *(uint2*)tmp;
}

// ---------------- transpose + scale x -> XW/XB1/XB0 fp16 [bb][d][t] ----------------
__global__ void k_xsplit(const float* __restrict__ x) {
    int bb = blockIdx.z;
    int tB = blockIdx.x * 32, dB = blockIdx.y * 32;
    __shared__ float s[32][33];
    int lr = threadIdx.x >> 5, lc = threadIdx.x & 31;
#pragma unroll
    for (int j = 0; j < 4; j++)
        s[lr + j * 8][lc] = x[src_row(bb, tB + lr + j * 8) * DIN + dB + lc];
    __syncthreads();
    int t = tB + lc;
    int c = t >> 8, tk = t & 255;
#pragma unroll
    for (int j = 0; j < 4; j++) {
        int d = dB + lr + j * 8;
        int h = d >> 7;
        float v = s[lc][lr + j * 8];
        size_t si = ((size_t)bb * NH + h) * LSEQ + t;
        size_t oi = ((size_t)bb * DIN + d) * LSEQ + t;
        g_XW [oi] = __float2half_rn(v * g_Wst[si]);
        g_XB1[oi] = __float2half_rn(v * g_W1[si]);
        if (tk < 128)
            g_XB0[(((size_t)bb * DIN + d) * NCH + c) * 128 + tk] = __float2half_rn(v * g_W0[si]);
    }
}

// ---------------- transpose B -> Bt fp16 [z][n][k] ----------------
__global__ void k_btsplit(const float* __restrict__ BC) {
    int z = blockIdx.z;
    int c = z % NCH, bb = z / NCH;
    int kB = blockIdx.x * 32, nB = blockIdx.y * 32;
    __shared__ float s[32][33];
    int lr = threadIdx.x >> 5, lc = threadIdx.x & 31;
#pragma unroll
    for (int j = 0; j < 4; j++)
        s[lr + j * 8][lc] = BC[src_row(bb, c * CHUNK_ + kB + lr + j * 8) * (2 * NSTATE) + nB + lc];
    __syncthreads();
#pragma unroll
    for (int j = 0; j < 4; j++)
        g_Btf[((size_t)z * NSTATE + nB + lr + j * 8) * CHUNK_ + kB + lc] =
            __float2half_rn(s[lc][lr + j * 8]);
}

// ---------------- CB GEMM: g_CB[z][i][k] = sum_n C[i,n] B[k,n] ----------------
__global__ void __launch_bounds__(256, 2) k_cb() {
    int iT = blockIdx.x, kT = blockIdx.y, z = blockIdx.z;
    if (iT == 0 && kT == 1) return;
    int c = z % NCH, bb = z / NCH;
    auto src = [&](int tile, int row, int kb) -> const hf* {
        if (tile == 0)
            return g_BCf + src_row(bb, c * CHUNK_ + iT * 128 + row) * (2 * NSTATE) + NSTATE + kb * 32;
        return g_BCf + src_row(bb, c * CHUNK_ + kT * 128 + row) * (2 * NSTATE) + kb * 32;
    };
    gemm128<false>(NSTATE / 32, src,
                   g_CB + ((size_t)z * CHUNK_ + iT * 128) * CHUNK_ + kT * 128, CHUNK_, nullptr);
}

// ---------------- mask + convert CB ----------------
__global__ void k_cbsplit() {
    int i = blockIdx.x, z = blockIdx.y;
    int k = threadIdx.x;
    size_t o = ((size_t)z * CHUNK_ + i) * CHUNK_ + k;
    g_CBf[o] = __float2half_rn((k <= i) ? g_CB[o] : 0.f);
}

// ---------------- states GEMM: g_S[z][h][p][n] = sum_k XW[p,k] Bt[n,k] ----------------
__global__ void __launch_bounds__(256, 2) k_states() {
    int nT = blockIdx.x, h = blockIdx.y, z = blockIdx.z;
    int c = z % NCH, bb = z / NCH;
    auto src = [&](int tile, int row, int kb) -> const hf* {
        if (tile == 0)
            return g_XW + ((size_t)bb * DIN + h * 128 + row) * LSEQ + c * CHUNK_ + kb * 32;
        return g_Btf + ((size_t)z * NSTATE + nT * 128 + row) * CHUNK_ + kb * 32;
    };
    gemm128<false>(CHUNK_ / 32, src,
                   g_S + (size_t)(z * NH + h) * HD * NSTATE + nT * 128, NSTATE, nullptr);
}

// ---------------- inter-chunk scan: g_S -> scaled prev fp16 ----------------
__global__ void k_scan() {
    int idx = blockIdx.x * blockDim.x + threadIdx.x;
    int n = idx & (NSTATE - 1);
    int p = (idx >> 8) & (HD - 1);
    int h = (idx >> 15) & (NH - 1);
    int bb = idx >> 19;
    size_t rest = ((size_t)h * HD + p) * NSTATE + n;
    const size_t stride = (size_t)NH * HD * NSTATE;
    float carry = 0.f;
    for (int c = 0; c < NCH; c++) {
        int zh = (bb * NCH + c) * NH + h;
        size_t off = (size_t)(bb * NCH + c) * stride + rest;
        float sv = g_S[off];
        g_P0[off] = __float2half_rn(carry * g_PS[zh * 2]);
        g_P1[off] = __float2half_rn(carry * g_PS[zh * 2 + 1]);
        carry = carry * g_cd[zh] + sv;
    }
}

// ---------------- y GEMM: ybuf = e2 * ( CBm@XBm + C@(e^m prev) ) ----------------
__global__ void __launch_bounds__(256, 2) k_y() {
    int iT = blockIdx.x, h = blockIdx.y, z = blockIdx.z;
    int c = z % NCH, bb = z / NCH;
    const int p0kb = iT ? 8 : 4;
    auto src = [&](int tile, int row, int kb) -> const hf* {
        if (kb < p0kb) {
            if (tile == 0)
                return g_CBf + ((size_t)z * CHUNK_ + iT * 128 + row) * CHUNK_ + kb * 32;
            if (iT)
                return g_XB1 + ((size_t)bb * DIN + h * 128 + row) * LSEQ + c * CHUNK_ + kb * 32;
            return g_XB0 + (((size_t)bb * DIN + h * 128 + row) * NCH + c) * 128 + kb * 32;
        }
        int n0 = (kb - p0kb) * 32;
        if (tile == 0)
            return g_BCf + src_row(bb, c * CHUNK_ + iT * 128 + row) * (2 * NSTATE) + NSTATE + n0;
        const hf* P = iT ? g_P1 : g_P0;
        return P + ((size_t)(z * NH + h) * HD + row) * NSTATE + n0;
    };
    int t0 = c * CHUNK_ + iT * 128;
    gemm128<true>(p0kb + NSTATE / 32, src,
                  g_ybuf + ((size_t)(bb * NH + h) * LSEQ + t0) * HD, HD,
                  g_E2 + (size_t)(bb * NH + h) * LSEQ + t0);
}

// ---------------- final combine ----------------
__global__ void k_final(const float* __restrict__ x, const float* __restrict__ W,
                        const float* __restrict__ Dp, float* __restrict__ out) {
    int t = blockIdx.x, b = blockIdx.y;
    __shared__ float xs[DIN];
    __shared__ float gate[NH];
    const float* xrow = x + ((size_t)b * LSEQ + t) * DIN;
    for (int d = threadIdx.x; d < DIN; d += 256) xs[d] = xrow[d];
    __syncthreads();
    int warp = threadIdx.x / 32, lane = threadIdx.x % 32;
#pragma unroll
    for (int hh = 0; hh < 2; hh++) {
        int h = warp * 2 + hh;
        const float* wrow = W + (size_t)h * DIN;
        float acc = 0.f;
        for (int d = lane; d < DIN; d += 32) acc += xs[d] * wrow[d];
#pragma unroll
        for (int o = 16; o; o >>= 1) acc += __shfl_down_sync(0xFFFFFFFFu, acc, o);
        if (lane == 0) gate[h] = acc + Dp[h];
    }
    __syncthreads();
    int tb = LSEQ - 1 - t;
    float* orow = out + ((size_t)b * LSEQ + t) * DIN;
    for (int d = threadIdx.x; d < DIN; d += 256) {
        int h = d >> 7, p = d & 127;
        float v = xs[d] * gate[h];
        if (t > 0)
            v += __half2float(g_ybuf[((size_t)(b * NH + h) * LSEQ + (t - 1)) * HD + p]);
        if (tb > 0)
            v += __half2float(g_ybuf[((size_t)((b + 2) * NH + h) * LSEQ + (tb - 1)) * HD + p]);
        orow[d] = v;
    }
}

// ---------------- launch ----------------
extern "C" void kernel_launch(void* const* d_in, const int* in_sizes, int n_in,
                              void* d_out, int out_size) {
    const float* x     = (const float*)d_in[0];
    const float* BC    = (const float*)d_in[1];
    const float* dt    = (const float*)d_in[2];
    const float* A_log = (const float*)d_in[3];
    const float* Dv    = (const float*)d_in[4];
    const float* W     = (const float*)d_in[5];
    float* out = (float*)d_out;

    cudaFuncSetAttribute(k_cb,     cudaFuncAttributeMaxDynamicSharedMemorySize, SMEM_GG);
    cudaFuncSetAttribute(k_states, cudaFuncAttributeMaxDynamicSharedMemorySize, SMEM_GG);
    cudaFuncSetAttribute(k_y,      cudaFuncAttributeMaxDynamicSharedMemorySize, SMEM_YY);

    k_pre     <<<dim3(NCH, NH, NBB), 256>>>(dt, A_log);
    k_split_bc<<<dim3(LSEQ, BSZ), 128>>>(BC);
    k_xsplit  <<<dim3(LSEQ / 32, DIN / 32, NBB), 256>>>(x);
    k_btsplit <<<dim3(8, 8, ZTOT), 256>>>(BC);
    k_cb      <<<dim3(2, 2, ZTOT), 256, SMEM_GG>>>();
    k_cbsplit <<<dim3(CHUNK_, ZTOT), 256>>>();
    k_states  <<<dim3(2, NH, ZTOT), 256, SMEM_GG>>>();
    k_scan    <<<(NBB * NH * HD * NSTATE) / 256, 256>>>();
    k_y       <<<dim3(2, NH, ZTOT), 256, SMEM_YY>>>();
    k_final   <<<dim3(LSEQ, BSZ), 256>>>(x, W, Dv, out);
}